// round 3
// baseline (speedup 1.0000x reference)
#include <cuda_runtime.h>
#include <cuda_bf16.h>

#define KL  128
#define TPB 128

using u64 = unsigned long long;

// ---- f32x2 packed math (sm_100a) ------------------------------------------
__device__ __forceinline__ u64 pk(float lo, float hi) {
    u64 r; asm("mov.b64 %0, {%1, %2};" : "=l"(r) : "f"(lo), "f"(hi)); return r;
}
__device__ __forceinline__ void upk(u64 v, float& lo, float& hi) {
    asm("mov.b64 {%0, %1}, %2;" : "=f"(lo), "=f"(hi) : "l"(v));
}
__device__ __forceinline__ u64 ffma2(u64 a, u64 b, u64 c) {
    u64 d; asm("fma.rn.f32x2 %0, %1, %2, %3;" : "=l"(d) : "l"(a), "l"(b), "l"(c)); return d;
}
__device__ __forceinline__ u64 fmul2(u64 a, u64 b) {
    u64 d; asm("mul.rn.f32x2 %0, %1, %2;" : "=l"(d) : "l"(a), "l"(b)); return d;
}
__device__ __forceinline__ u64 fadd2(u64 a, u64 b) {
    u64 d; asm("add.rn.f32x2 %0, %1, %2;" : "=l"(d) : "l"(a), "l"(b)); return d;
}

// 4 pixels per thread (two f32x2 pairs A,B). Lights duplicated in shared as
// (x,x) pairs: 3 LDS.128 per light now amortized over 4 pixels.
__global__ __launch_bounds__(TPB)
void blinn_phong_envmap_kernel(
    const float* __restrict__ pixel_normals,    // (HW,3)
    const float* __restrict__ pixel_directions, // (HW,3)
    const float* __restrict__ camera_position,  // (3,)
    const float* __restrict__ light_directions, // (K,3)
    const float* __restrict__ light_colors,     // (K,3)
    const float* __restrict__ shininess_p,
    const float* __restrict__ kd_p,
    const float* __restrict__ ks_p,
    float* __restrict__ out,                    // colors (HW,3) then n (HW,3)
    int npix)                                   // 512*512, divisible by 4
{
    // Per light: q0=(Lx,Lx,Ly,Ly) q1=(Lz,Lz,Cx,Cx) q2=(Cy,Cy,Cz,Cz)
    __shared__ float4 sl[KL * 3];
    const int tid = threadIdx.x;
    for (int i = tid; i < KL; i += TPB) {
        float Lx = light_directions[3*i], Ly = light_directions[3*i+1], Lz = light_directions[3*i+2];
        float Cx = light_colors[3*i],     Cy = light_colors[3*i+1],     Cz = light_colors[3*i+2];
        sl[3*i]   = make_float4(Lx, Lx, Ly, Ly);
        sl[3*i+1] = make_float4(Lz, Lz, Cx, Cx);
        sl[3*i+2] = make_float4(Cy, Cy, Cz, Cz);
    }
    __syncthreads();

    const int t = blockIdx.x * TPB + tid;    // 4-pixel group index
    if (4 * t >= npix) return;

    const float shin = __ldg(shininess_p);
    const float kd   = __ldg(kd_p);
    const float ks   = __ldg(ks_p);
    const float cx = __ldg(camera_position + 0);
    const float cy = __ldg(camera_position + 1);
    const float cz = __ldg(camera_position + 2);

    // ---- load 4 pixels (12 floats per array) via 3 aligned float4 ----
    const float4* pn4 = (const float4*)pixel_normals;
    const float4* pd4 = (const float4*)pixel_directions;
    float4 a0 = pn4[3*t], a1 = pn4[3*t+1], a2 = pn4[3*t+2];
    float n0x=a0.x, n0y=a0.y, n0z=a0.z;
    float n1x=a0.w, n1y=a1.x, n1z=a1.y;
    float n2x=a1.z, n2y=a1.w, n2z=a2.x;
    float n3x=a2.y, n3y=a2.z, n3z=a2.w;
    {
        float i0 = rsqrtf(fmaxf(n0x*n0x + n0y*n0y + n0z*n0z, 1e-12f));
        float i1 = rsqrtf(fmaxf(n1x*n1x + n1y*n1y + n1z*n1z, 1e-12f));
        float i2 = rsqrtf(fmaxf(n2x*n2x + n2y*n2y + n2z*n2z, 1e-12f));
        float i3 = rsqrtf(fmaxf(n3x*n3x + n3y*n3y + n3z*n3z, 1e-12f));
        n0x*=i0; n0y*=i0; n0z*=i0;  n1x*=i1; n1y*=i1; n1z*=i1;
        n2x*=i2; n2y*=i2; n2z*=i2;  n3x*=i3; n3y*=i3; n3z*=i3;
    }
    float4 b0 = pd4[3*t], b1 = pd4[3*t+1], b2 = pd4[3*t+2];
    float v0x=cx-b0.x, v0y=cy-b0.y, v0z=cz-b0.z;
    float v1x=cx-b0.w, v1y=cy-b1.x, v1z=cz-b1.y;
    float v2x=cx-b1.z, v2y=cy-b1.w, v2z=cz-b2.x;
    float v3x=cx-b2.y, v3y=cy-b2.z, v3z=cz-b2.w;
    {
        float j0 = rsqrtf(fmaxf(v0x*v0x + v0y*v0y + v0z*v0z, 1e-12f));
        float j1 = rsqrtf(fmaxf(v1x*v1x + v1y*v1y + v1z*v1z, 1e-12f));
        float j2 = rsqrtf(fmaxf(v2x*v2x + v2y*v2y + v2z*v2z, 1e-12f));
        float j3 = rsqrtf(fmaxf(v3x*v3x + v3y*v3y + v3z*v3z, 1e-12f));
        v0x*=j0; v0y*=j0; v0z*=j0;  v1x*=j1; v1y*=j1; v1z*=j1;
        v2x*=j2; v2y*=j2; v2z*=j2;  v3x*=j3; v3y*=j3; v3z*=j3;
    }

    // packed state: pair A = (px0,px1), pair B = (px2,px3)
    const u64 nxA = pk(n0x,n1x), nyA = pk(n0y,n1y), nzA = pk(n0z,n1z);
    const u64 nxB = pk(n2x,n3x), nyB = pk(n2y,n3y), nzB = pk(n2z,n3z);
    const u64 vxA = pk(v0x,v1x), vyA = pk(v0y,v1y), vzA = pk(v0z,v1z);
    const u64 vxB = pk(v2x,v3x), vyB = pk(v2y,v3y), vzB = pk(v2z,v3z);
    const u64 nvA = pk(n0x*v0x + n0y*v0y + n0z*v0z, n1x*v1x + n1y*v1y + n1z*v1z);
    const u64 nvB = pk(n2x*v2x + n2y*v2y + n2z*v2z, n3x*v3x + n3y*v3y + n3z*v3z);
    const u64 two2 = pk(2.0f, 2.0f);

    const float nf = (shin + 2.0f) / (4.0f * (2.0f - __expf(-shin * 0.5f)));
    const float B  = nf * ks;
    const u64 kd2 = pk(kd, kd);
    const u64 B2  = pk(B, B);

    u64 arA=0ull, agA=0ull, abA=0ull;
    u64 arB=0ull, agB=0ull, abB=0ull;

    const ulonglong2* __restrict__ slp = (const ulonglong2*)sl;
#pragma unroll 2
    for (int k = 0; k < KL; k++) {
        ulonglong2 q0 = slp[3*k];      // (Lx,Lx) (Ly,Ly)
        ulonglong2 q1 = slp[3*k+1];    // (Lz,Lz) (Cx,Cx)
        ulonglong2 q2 = slp[3*k+2];    // (Cy,Cy) (Cz,Cz)

        u64 dlA = fmul2(nxA, q0.x);  dlA = ffma2(nyA, q0.y, dlA);  dlA = ffma2(nzA, q1.x, dlA);
        u64 dlB = fmul2(nxB, q0.x);  dlB = ffma2(nyB, q0.y, dlB);  dlB = ffma2(nzB, q1.x, dlB);
        u64 cA  = fmul2(vxA, q0.x);  cA  = ffma2(vyA, q0.y, cA);   cA  = ffma2(vzA, q1.x, cA);
        u64 cB  = fmul2(vxB, q0.x);  cB  = ffma2(vyB, q0.y, cB);   cB  = ffma2(vzB, q1.x, cB);

        u64 h2A = ffma2(two2, cA, two2);   // |v+L|^2 = 2 + 2 v.L (unit vectors)
        u64 h2B = ffma2(two2, cB, two2);
        u64 mA  = fadd2(nvA, dlA);         // n.(v+L)
        u64 mB  = fadd2(nvB, dlB);

        float h0,h1,h2,h3, m0,m1,m2,m3, d0,d1,d2,d3;
        upk(h2A,h0,h1); upk(h2B,h2,h3);
        upk(mA,m0,m1);  upk(mB,m2,m3);
        upk(dlA,d0,d1); upk(dlB,d2,d3);

        float s0 = __saturatef(m0 * rsqrtf(fmaxf(h0, 1e-12f)));
        float s1 = __saturatef(m1 * rsqrtf(fmaxf(h1, 1e-12f)));
        float s2 = __saturatef(m2 * rsqrtf(fmaxf(h2, 1e-12f)));
        float s3 = __saturatef(m3 * rsqrtf(fmaxf(h3, 1e-12f)));
        float sp0 = __powf(s0, shin);
        float sp1 = __powf(s1, shin);
        float sp2 = __powf(s2, shin);
        float sp3 = __powf(s3, shin);

        u64 dA  = pk(__saturatef(d0), __saturatef(d1));
        u64 dB  = pk(__saturatef(d2), __saturatef(d3));
        u64 wA  = ffma2(kd2, dA, fmul2(B2, pk(sp0, sp1)));
        u64 wB  = ffma2(kd2, dB, fmul2(B2, pk(sp2, sp3)));

        arA = ffma2(q1.y, wA, arA);  agA = ffma2(q2.x, wA, agA);  abA = ffma2(q2.y, wA, abA);
        arB = ffma2(q1.y, wB, arB);  agB = ffma2(q2.x, wB, agB);  abB = ffma2(q2.y, wB, abB);
    }

    float c0r,c1r,c0g,c1g,c0b,c1b, c2r,c3r,c2g,c3g,c2b,c3b;
    upk(arA,c0r,c1r); upk(agA,c0g,c1g); upk(abA,c0b,c1b);
    upk(arB,c2r,c3r); upk(agB,c2g,c3g); upk(abB,c2b,c3b);

    float4* __restrict__ o4 = (float4*)out;
    o4[3*t]   = make_float4(c0r, c0g, c0b, c1r);
    o4[3*t+1] = make_float4(c1g, c1b, c2r, c2g);
    o4[3*t+2] = make_float4(c2b, c3r, c3g, c3b);

    float4* __restrict__ no4 = (float4*)(out + (size_t)3 * npix);
    no4[3*t]   = make_float4(n0x, n0y, n0z, n1x);
    no4[3*t+1] = make_float4(n1y, n1z, n2x, n2y);
    no4[3*t+2] = make_float4(n2z, n3x, n3y, n3z);
}

extern "C" void kernel_launch(void* const* d_in, const int* in_sizes, int n_in,
                              void* d_out, int out_size)
{
    const float* pixel_normals    = (const float*)d_in[0];
    const float* pixel_directions = (const float*)d_in[1];
    const float* camera_position  = (const float*)d_in[2];
    const float* light_directions = (const float*)d_in[3];
    const float* light_colors     = (const float*)d_in[4];
    const float* shininess        = (const float*)d_in[5];
    const float* kd               = (const float*)d_in[6];
    const float* ks               = (const float*)d_in[7];

    const int npix   = in_sizes[0] / 3;     // 262144
    const int groups = npix / 4;
    const int blocks = (groups + TPB - 1) / TPB;

    blinn_phong_envmap_kernel<<<blocks, TPB>>>(
        pixel_normals, pixel_directions, camera_position,
        light_directions, light_colors, shininess, kd, ks,
        (float*)d_out, npix);
}

// round 4
// speedup vs baseline: 1.1701x; 1.1701x over previous
#include <cuda_runtime.h>
#include <cuda_bf16.h>

#define KL   128
#define TPB  256
#define HALF 128   // threads per light-half

using u64 = unsigned long long;

// ---- f32x2 packed math (sm_100a) ------------------------------------------
__device__ __forceinline__ u64 pk(float lo, float hi) {
    u64 r; asm("mov.b64 %0, {%1, %2};" : "=l"(r) : "f"(lo), "f"(hi)); return r;
}
__device__ __forceinline__ void upk(u64 v, float& lo, float& hi) {
    asm("mov.b64 {%0, %1}, %2;" : "=f"(lo), "=f"(hi) : "l"(v));
}
__device__ __forceinline__ u64 ffma2(u64 a, u64 b, u64 c) {
    u64 d; asm("fma.rn.f32x2 %0, %1, %2, %3;" : "=l"(d) : "l"(a), "l"(b), "l"(c)); return d;
}
__device__ __forceinline__ u64 fmul2(u64 a, u64 b) {
    u64 d; asm("mul.rn.f32x2 %0, %1, %2;" : "=l"(d) : "l"(a), "l"(b)); return d;
}
__device__ __forceinline__ u64 fadd2(u64 a, u64 b) {
    u64 d; asm("add.rn.f32x2 %0, %1, %2;" : "=l"(d) : "l"(a), "l"(b)); return d;
}

// 2 pixels per thread; light loop SPLIT across thread halves:
//   thread t (<128) and t+128 shade the same 2 pixels over lights [0,64) / [64,128).
// Upper half deposits its partial RGB sums in shared; lower half combines+stores.
__global__ __launch_bounds__(TPB)
void blinn_phong_envmap_kernel(
    const float* __restrict__ pixel_normals,
    const float* __restrict__ pixel_directions,
    const float* __restrict__ camera_position,
    const float* __restrict__ light_directions,
    const float* __restrict__ light_colors,
    const float* __restrict__ shininess_p,
    const float* __restrict__ kd_p,
    const float* __restrict__ ks_p,
    float* __restrict__ out,                    // colors (HW,3) then n (HW,3)
    int npix)
{
    // Per light: q0=(Lx,Lx,Ly,Ly) q1=(Lz,Lz,Cx,Cx) q2=(Cy,Cy,Cz,Cz)
    __shared__ float4 sl[KL * 3];
    __shared__ u64 spart[HALF][3];     // upper half's partial RGB (packed px0,px1)

    const int tid = threadIdx.x;
    for (int i = tid; i < KL; i += TPB) {
        float Lx = light_directions[3*i], Ly = light_directions[3*i+1], Lz = light_directions[3*i+2];
        float Cx = light_colors[3*i],     Cy = light_colors[3*i+1],     Cz = light_colors[3*i+2];
        sl[3*i]   = make_float4(Lx, Lx, Ly, Ly);
        sl[3*i+1] = make_float4(Lz, Lz, Cx, Cx);
        sl[3*i+2] = make_float4(Cy, Cy, Cz, Cz);
    }
    __syncthreads();

    const int lane  = tid & (HALF - 1);          // 0..127: pixel-pair slot in block
    const int halfi = tid >> 7;                  // 0 or 1: light half
    const int t = blockIdx.x * HALF + lane;      // global pixel-pair index
    const bool active = (2 * t < npix);

    const float shin = __ldg(shininess_p);
    const float kd   = __ldg(kd_p);
    const float ks   = __ldg(ks_p);
    const float cx = __ldg(camera_position + 0);
    const float cy = __ldg(camera_position + 1);
    const float cz = __ldg(camera_position + 2);

    u64 ar = 0ull, ag = 0ull, ab = 0ull;
    float n0x=0, n0y=0, n0z=0, n1x=0, n1y=0, n1z=0;

    if (active) {
        const float2* pn2 = (const float2*)pixel_normals;
        const float2* pd2 = (const float2*)pixel_directions;
        float2 a0 = pn2[3*t], a1 = pn2[3*t+1], a2 = pn2[3*t+2];
        n0x = a0.x; n0y = a0.y; n0z = a1.x;
        n1x = a1.y; n1y = a2.x; n1z = a2.y;
        {
            float i0 = rsqrtf(fmaxf(n0x*n0x + n0y*n0y + n0z*n0z, 1e-12f));
            float i1 = rsqrtf(fmaxf(n1x*n1x + n1y*n1y + n1z*n1z, 1e-12f));
            n0x*=i0; n0y*=i0; n0z*=i0;  n1x*=i1; n1y*=i1; n1z*=i1;
        }
        float2 b0 = pd2[3*t], b1 = pd2[3*t+1], b2 = pd2[3*t+2];
        float v0x=cx-b0.x, v0y=cy-b0.y, v0z=cz-b1.x;
        float v1x=cx-b1.y, v1y=cy-b2.x, v1z=cz-b2.y;
        {
            float j0 = rsqrtf(fmaxf(v0x*v0x + v0y*v0y + v0z*v0z, 1e-12f));
            float j1 = rsqrtf(fmaxf(v1x*v1x + v1y*v1y + v1z*v1z, 1e-12f));
            v0x*=j0; v0y*=j0; v0z*=j0;  v1x*=j1; v1y*=j1; v1z*=j1;
        }
        const u64 nx2 = pk(n0x,n1x), ny2 = pk(n0y,n1y), nz2 = pk(n0z,n1z);
        const u64 vx2 = pk(v0x,v1x), vy2 = pk(v0y,v1y), vz2 = pk(v0z,v1z);
        const u64 nv2 = pk(n0x*v0x + n0y*v0y + n0z*v0z,
                           n1x*v1x + n1y*v1y + n1z*v1z);
        const u64 two2 = pk(2.0f, 2.0f);

        const float nf = (shin + 2.0f) / (4.0f * (2.0f - __expf(-shin * 0.5f)));
        const float B  = nf * ks;
        const u64 kd2 = pk(kd, kd);
        const u64 B2  = pk(B, B);

        const ulonglong2* __restrict__ slp = (const ulonglong2*)sl + (size_t)3 * (halfi * (KL/2));
#pragma unroll 4
        for (int k = 0; k < KL/2; k++) {
            ulonglong2 q0 = slp[3*k];      // (Lx,Lx) (Ly,Ly)
            ulonglong2 q1 = slp[3*k+1];    // (Lz,Lz) (Cx,Cx)
            ulonglong2 q2 = slp[3*k+2];    // (Cy,Cy) (Cz,Cz)

            u64 dl2 = fmul2(nx2, q0.x);
            dl2 = ffma2(ny2, q0.y, dl2);
            dl2 = ffma2(nz2, q1.x, dl2);
            u64 c2 = fmul2(vx2, q0.x);
            c2 = ffma2(vy2, q0.y, c2);
            c2 = ffma2(vz2, q1.x, c2);

            u64 h22 = ffma2(two2, c2, two2);   // |v+L|^2 = 2 + 2 v.L
            u64 m2  = fadd2(nv2, dl2);         // n.(v+L)

            float h2a, h2b, ma, mb, da, db_;
            upk(h22, h2a, h2b); upk(m2, ma, mb); upk(dl2, da, db_);

            float sa  = __saturatef(ma * rsqrtf(fmaxf(h2a, 1e-12f)));
            float sb_ = __saturatef(mb * rsqrtf(fmaxf(h2b, 1e-12f)));
            float spa = __powf(sa,  shin);
            float spb = __powf(sb_, shin);

            u64 d2  = pk(__saturatef(da), __saturatef(db_));
            u64 w2  = ffma2(kd2, d2, fmul2(B2, pk(spa, spb)));

            ar = ffma2(q1.y, w2, ar);
            ag = ffma2(q2.x, w2, ag);
            ab = ffma2(q2.y, w2, ab);
        }
    }

    // ---- combine halves ----
    if (halfi == 1) {
        spart[lane][0] = ar;
        spart[lane][1] = ag;
        spart[lane][2] = ab;
    }
    __syncthreads();

    if (halfi == 0 && active) {
        ar = fadd2(ar, spart[lane][0]);
        ag = fadd2(ag, spart[lane][1]);
        ab = fadd2(ab, spart[lane][2]);

        float c0r,c1r,c0g,c1g,c0b,c1b;
        upk(ar,c0r,c1r); upk(ag,c0g,c1g); upk(ab,c0b,c1b);

        float2* __restrict__ o2 = (float2*)out;
        o2[3*t]   = make_float2(c0r, c0g);
        o2[3*t+1] = make_float2(c0b, c1r);
        o2[3*t+2] = make_float2(c1g, c1b);

        float2* __restrict__ no2 = (float2*)(out + (size_t)3 * npix);
        no2[3*t]   = make_float2(n0x, n0y);
        no2[3*t+1] = make_float2(n0z, n1x);
        no2[3*t+2] = make_float2(n1y, n1z);
    }
}

extern "C" void kernel_launch(void* const* d_in, const int* in_sizes, int n_in,
                              void* d_out, int out_size)
{
    const float* pixel_normals    = (const float*)d_in[0];
    const float* pixel_directions = (const float*)d_in[1];
    const float* camera_position  = (const float*)d_in[2];
    const float* light_directions = (const float*)d_in[3];
    const float* light_colors     = (const float*)d_in[4];
    const float* shininess        = (const float*)d_in[5];
    const float* kd               = (const float*)d_in[6];
    const float* ks               = (const float*)d_in[7];

    const int npix  = in_sizes[0] / 3;          // 262144
    const int pairs = npix / 2;                 // 131072
    const int blocks = (pairs + HALF - 1) / HALF;  // 1024 blocks x 256 threads

    blinn_phong_envmap_kernel<<<blocks, TPB>>>(
        pixel_normals, pixel_directions, camera_position,
        light_directions, light_colors, shininess, kd, ks,
        (float*)d_out, npix);
}